// round 1
// baseline (speedup 1.0000x reference)
#include <cuda_runtime.h>
#include <math.h>

#define BSZ 2
#define LSEQ 1024
#define DMODEL 1024
#define DINNER 2048
#define DSTATE 64
#define NHEADS 32
#define HEADDIM 64
#define CONVCH 2176
#define DPROJ 4256
#define NTOK 2048    // BSZ*LSEQ

// ---------------- scratch (device globals; no runtime allocation) -------------
__device__ float g_zx[2][(size_t)NTOK * DPROJ];    // zxbcdt per direction
__device__ float g_xbc[2][(size_t)NTOK * CONVCH];  // post-conv silu(xBC)
__device__ float g_dt[2][NTOK * NHEADS];
__device__ float g_dA[2][NTOK * NHEADS];
__device__ float g_y[2][(size_t)NTOK * DINNER];    // scan output + D-skip
__device__ float g_gn[2][(size_t)NTOK * DINNER];   // gated-rmsnormed
__device__ float g_cat[(size_t)NTOK * 2 * DMODEL]; // concat of per-dir outputs

// ---------------- generic fp32 SGEMM: C = A[M,K] @ B[K,N] (+bias) -------------
// 128x128 block tile, BK=8, 256 threads, 8x8 microtile.
// revA: A rows are sequence-reversed per batch (b*1024 + (1023-l))
// revC: C rows written sequence-reversed per batch
__global__ __launch_bounds__(256, 1)
void sgemm128(const float* __restrict__ A, int lda,
              const float* __restrict__ B, int ldb,
              float* __restrict__ C, int ldc, int c_col_off,
              int M, int N, int K, int revA, int revC,
              const float* __restrict__ bias)
{
    __shared__ float As[8][128];
    __shared__ float Bs[8][128];

    const int tid = threadIdx.x;
    const int bn = blockIdx.x * 128;
    const int bm = blockIdx.y * 128;

    // A staging: each thread loads one float4 (row = tid/2, kcol = (tid&1)*4)
    const int a_row = tid >> 1;
    const int a_col = (tid & 1) * 4;
    int am = bm + a_row;
    if (revA) { int bb = am >> 10; int ll = am & 1023; am = (bb << 10) + (1023 - ll); }
    const float* Aptr = A + (size_t)am * lda + a_col;

    // B staging: row = tid/32, col4 = (tid&31)*4
    const int b_row = tid >> 5;
    const int b_col = (tid & 31) * 4;
    const float* Bptr = B + (size_t)b_row * ldb + (bn + b_col);
    const bool b_ok = (bn + b_col) < N;   // N % 4 == 0 in all uses

    float acc[8][8];
#pragma unroll
    for (int i = 0; i < 8; i++)
#pragma unroll
        for (int j = 0; j < 8; j++) acc[i][j] = 0.f;

    const int tx = tid & 15;
    const int ty = tid >> 4;

    for (int k0 = 0; k0 < K; k0 += 8) {
        float4 av = *(const float4*)(Aptr + k0);
        float4 bv = make_float4(0.f, 0.f, 0.f, 0.f);
        if (b_ok) bv = *(const float4*)(Bptr + (size_t)k0 * ldb);

        As[a_col + 0][a_row] = av.x;
        As[a_col + 1][a_row] = av.y;
        As[a_col + 2][a_row] = av.z;
        As[a_col + 3][a_row] = av.w;
        *(float4*)&Bs[b_row][b_col] = bv;
        __syncthreads();

#pragma unroll
        for (int k = 0; k < 8; k++) {
            float a[8], b[8];
            float4 a0 = *(const float4*)&As[k][ty * 8];
            float4 a1 = *(const float4*)&As[k][ty * 8 + 4];
            float4 b0 = *(const float4*)&Bs[k][tx * 8];
            float4 b1 = *(const float4*)&Bs[k][tx * 8 + 4];
            a[0]=a0.x;a[1]=a0.y;a[2]=a0.z;a[3]=a0.w;a[4]=a1.x;a[5]=a1.y;a[6]=a1.z;a[7]=a1.w;
            b[0]=b0.x;b[1]=b0.y;b[2]=b0.z;b[3]=b0.w;b[4]=b1.x;b[5]=b1.y;b[6]=b1.z;b[7]=b1.w;
#pragma unroll
            for (int i = 0; i < 8; i++)
#pragma unroll
                for (int j = 0; j < 8; j++)
                    acc[i][j] = fmaf(a[i], b[j], acc[i][j]);
        }
        __syncthreads();
    }

#pragma unroll
    for (int i = 0; i < 8; i++) {
        int m = bm + ty * 8 + i;
        int mw = m;
        if (revC) { int bb = m >> 10; int ll = m & 1023; mw = (bb << 10) + (1023 - ll); }
        float* Crow = C + (size_t)mw * ldc + c_col_off;
#pragma unroll
        for (int j = 0; j < 8; j++) {
            int n = bn + tx * 8 + j;
            if (n < N) {
                float v = acc[i][j];
                if (bias) v += bias[n];
                Crow[n] = v;
            }
        }
    }
}

// ---------------- conv (causal depthwise, 4 taps) + silu + dt/dA --------------
__global__ __launch_bounds__(256)
void conv_silu_dt(const float* __restrict__ cw0, const float* __restrict__ cb0,
                  const float* __restrict__ dtb0, const float* __restrict__ Al0,
                  const float* __restrict__ cw1, const float* __restrict__ cb1,
                  const float* __restrict__ dtb1, const float* __restrict__ Al1)
{
    const int dir = blockIdx.z;
    const int b = blockIdx.y;
    const int l = blockIdx.x;
    const float* cw  = dir ? cw1  : cw0;
    const float* cb  = dir ? cb1  : cb0;
    const float* dtb = dir ? dtb1 : dtb0;
    const float* Al  = dir ? Al1  : Al0;

    const float* zx = g_zx[dir];
    const int row = b * LSEQ + l;
    float* out = g_xbc[dir] + (size_t)row * CONVCH;

    for (int c = threadIdx.x; c < CONVCH; c += 256) {
        float acc = cb[c];
#pragma unroll
        for (int j = 0; j < 4; j++) {
            int ls = l - 3 + j;
            if (ls >= 0)
                acc = fmaf(cw[j * CONVCH + c],
                           zx[(size_t)(b * LSEQ + ls) * DPROJ + DINNER + c], acc);
        }
        out[c] = acc * (1.f / (1.f + expf(-acc)));   // silu
    }

    for (int h = threadIdx.x; h < NHEADS; h += 256) {
        float v = zx[(size_t)row * DPROJ + DINNER + CONVCH + h] + dtb[h];
        float dt = (v > 20.f) ? v : log1pf(expf(v));   // softplus
        g_dt[dir][row * NHEADS + h] = dt;
        g_dA[dir][row * NHEADS + h] = expf(-expf(Al[h]) * dt);
    }
}

// ---------------- sequential selective scan ----------------
// block = (h, b, dir); 256 threads: thread t -> p = t>>2, n-range [ (t&3)*16, +16 )
#define TCHUNK 16
__global__ __launch_bounds__(256)
void scan_kernel(const float* __restrict__ D0, const float* __restrict__ D1)
{
    const int h = blockIdx.x;
    const int b = blockIdx.y;
    const int dir = blockIdx.z;
    const float* xbc = g_xbc[dir];
    const float* dtp = g_dt[dir];
    const float* dAp = g_dA[dir];
    float* yout = g_y[dir];
    const float Dh = (dir ? D1 : D0)[h];

    __shared__ float Bs[TCHUNK][DSTATE];
    __shared__ float Cs[TCHUNK][DSTATE];
    __shared__ float Xs[TCHUNK][HEADDIM];
    __shared__ float dAs[TCHUNK], dts[TCHUNK];

    const int tid = threadIdx.x;
    const int p = tid >> 2;
    const int q = tid & 3;
    const int n0 = q * 16;

    float hs[16];
#pragma unroll
    for (int i = 0; i < 16; i++) hs[i] = 0.f;

    const int rowbase = b * LSEQ;
    for (int l0 = 0; l0 < LSEQ; l0 += TCHUNK) {
        for (int i = tid; i < TCHUNK * 64; i += 256) {
            int tt = i >> 6, j = i & 63;
            size_t r = (size_t)(rowbase + l0 + tt);
            Bs[tt][j] = xbc[r * CONVCH + DINNER + j];
            Cs[tt][j] = xbc[r * CONVCH + DINNER + DSTATE + j];
            Xs[tt][j] = xbc[r * CONVCH + h * HEADDIM + j];
        }
        if (tid < TCHUNK) {
            size_t r = (size_t)(rowbase + l0 + tid);
            dAs[tid] = dAp[r * NHEADS + h];
            dts[tid] = dtp[r * NHEADS + h];
        }
        __syncthreads();

#pragma unroll
        for (int tt = 0; tt < TCHUNK; tt++) {
            float xp = Xs[tt][p];
            float da = dAs[tt];
            float coef = dts[tt] * xp;
            float ysum = 0.f;
            const float4* Bv = (const float4*)&Bs[tt][n0];
            const float4* Cv = (const float4*)&Cs[tt][n0];
#pragma unroll
            for (int i4 = 0; i4 < 4; i4++) {
                float4 bb = Bv[i4];
                float4 cc = Cv[i4];
                hs[i4*4+0] = fmaf(da, hs[i4*4+0], coef * bb.x); ysum = fmaf(cc.x, hs[i4*4+0], ysum);
                hs[i4*4+1] = fmaf(da, hs[i4*4+1], coef * bb.y); ysum = fmaf(cc.y, hs[i4*4+1], ysum);
                hs[i4*4+2] = fmaf(da, hs[i4*4+2], coef * bb.z); ysum = fmaf(cc.z, hs[i4*4+2], ysum);
                hs[i4*4+3] = fmaf(da, hs[i4*4+3], coef * bb.w); ysum = fmaf(cc.w, hs[i4*4+3], ysum);
            }
            ysum += __shfl_xor_sync(0xffffffffu, ysum, 1);
            ysum += __shfl_xor_sync(0xffffffffu, ysum, 2);
            if (q == 0)
                yout[(size_t)(rowbase + l0 + tt) * DINNER + h * HEADDIM + p] =
                    ysum + Dh * xp;
        }
        __syncthreads();
    }
}

// ---------------- gated RMSNorm: gn = normw * (y*silu(z)) * rsqrt(mean+eps) ---
__global__ __launch_bounds__(256)
void gated_norm(const float* __restrict__ nw0, const float* __restrict__ nw1)
{
    const int dir = blockIdx.y;
    const int row = blockIdx.x;
    const float* nw = dir ? nw1 : nw0;
    const float* y = g_y[dir] + (size_t)row * DINNER;
    const float* z = g_zx[dir] + (size_t)row * DPROJ;   // z = first DINNER cols
    float* o = g_gn[dir] + (size_t)row * DINNER;

    float vals[8];
    float ss = 0.f;
#pragma unroll
    for (int i = 0; i < 8; i++) {
        int c = threadIdx.x + i * 256;
        float zz = z[c];
        float g = y[c] * (zz / (1.f + expf(-zz)));
        vals[i] = g;
        ss = fmaf(g, g, ss);
    }
#pragma unroll
    for (int o2 = 16; o2; o2 >>= 1) ss += __shfl_xor_sync(0xffffffffu, ss, o2);
    __shared__ float red[8];
    if ((threadIdx.x & 31) == 0) red[threadIdx.x >> 5] = ss;
    __syncthreads();
    float tot = red[0] + red[1] + red[2] + red[3] + red[4] + red[5] + red[6] + red[7];
    float scale = rsqrtf(tot * (1.f / DINNER) + 1e-5f);
#pragma unroll
    for (int i = 0; i < 8; i++) {
        int c = threadIdx.x + i * 256;
        o[c] = vals[i] * scale * nw[c];
    }
}

// ---------------- launch ----------------
extern "C" void kernel_launch(void* const* d_in, const int* in_sizes, int n_in,
                              void* d_out, int out_size)
{
    (void)in_sizes; (void)n_in; (void)out_size;
    const float* x      = (const float*)d_in[0];
    const float* fWin   = (const float*)d_in[1];
    const float* fconvw = (const float*)d_in[2];
    const float* fconvb = (const float*)d_in[3];
    const float* fdtb   = (const float*)d_in[4];
    const float* fAlog  = (const float*)d_in[5];
    const float* fD     = (const float*)d_in[6];
    const float* fnormw = (const float*)d_in[7];
    const float* fWout  = (const float*)d_in[8];
    const float* bWin   = (const float*)d_in[9];
    const float* bconvw = (const float*)d_in[10];
    const float* bconvb = (const float*)d_in[11];
    const float* bdtb   = (const float*)d_in[12];
    const float* bAlog  = (const float*)d_in[13];
    const float* bD     = (const float*)d_in[14];
    const float* bnormw = (const float*)d_in[15];
    const float* bWout  = (const float*)d_in[16];
    const float* Wo     = (const float*)d_in[17];
    const float* bo     = (const float*)d_in[18];
    float* out = (float*)d_out;

    float *zx, *gn, *cat;
    cudaGetSymbolAddress((void**)&zx, g_zx);
    cudaGetSymbolAddress((void**)&gn, g_gn);
    cudaGetSymbolAddress((void**)&cat, g_cat);
    float* zx0 = zx;
    float* zx1 = zx + (size_t)NTOK * DPROJ;
    float* gn0 = gn;
    float* gn1 = gn + (size_t)NTOK * DINNER;

    // 1) input projections (dir1 reads x sequence-reversed)
    dim3 g1((DPROJ + 127) / 128, NTOK / 128);
    sgemm128<<<g1, 256>>>(x, DMODEL, fWin, DPROJ, zx0, DPROJ, 0,
                          NTOK, DPROJ, DMODEL, 0, 0, nullptr);
    sgemm128<<<g1, 256>>>(x, DMODEL, bWin, DPROJ, zx1, DPROJ, 0,
                          NTOK, DPROJ, DMODEL, 1, 0, nullptr);

    // 2) causal conv + silu + dt/dA
    conv_silu_dt<<<dim3(LSEQ, BSZ, 2), 256>>>(fconvw, fconvb, fdtb, fAlog,
                                              bconvw, bconvb, bdtb, bAlog);

    // 3) selective scan
    scan_kernel<<<dim3(NHEADS, BSZ, 2), 256>>>(fD, bD);

    // 4) gated RMSNorm
    gated_norm<<<dim3(NTOK, 2), 256>>>(fnormw, bnormw);

    // 5) per-direction output projections into concat buffer (dir1 rows flipped back)
    dim3 g2(DMODEL / 128, NTOK / 128);
    sgemm128<<<g2, 256>>>(gn0, DINNER, fWout, DMODEL, cat, 2 * DMODEL, 0,
                          NTOK, DMODEL, DINNER, 0, 0, nullptr);
    sgemm128<<<g2, 256>>>(gn1, DINNER, bWout, DMODEL, cat, 2 * DMODEL, DMODEL,
                          NTOK, DMODEL, DINNER, 0, 1, nullptr);

    // 6) final projection + bias
    sgemm128<<<g2, 256>>>(cat, 2 * DMODEL, Wo, DMODEL, out, DMODEL, 0,
                          NTOK, DMODEL, 2 * DMODEL, 0, 0, bo);
}

// round 2
// speedup vs baseline: 1.1244x; 1.1244x over previous
#include <cuda_runtime.h>
#include <math.h>

#define BSZ 2
#define LSEQ 1024
#define DMODEL 1024
#define DINNER 2048
#define DSTATE 64
#define NHEADS 32
#define HEADDIM 64
#define CONVCH 2176
#define DPROJ 4256
#define NTOK 2048    // BSZ*LSEQ

typedef unsigned long long u64;

// ---------------- f32x2 packed-math helpers (sm_103a FFMA2 path) --------------
__device__ __forceinline__ u64 dup2(float v) {
    u64 r; asm("mov.b64 %0, {%1, %1};" : "=l"(r) : "f"(v)); return r;
}
__device__ __forceinline__ u64 fma2(u64 a, u64 b, u64 c) {
    u64 d; asm("fma.rn.f32x2 %0, %1, %2, %3;" : "=l"(d) : "l"(a), "l"(b), "l"(c)); return d;
}
__device__ __forceinline__ u64 mul2(u64 a, u64 b) {
    u64 d; asm("mul.rn.f32x2 %0, %1, %2;" : "=l"(d) : "l"(a), "l"(b)); return d;
}
__device__ __forceinline__ void unpack2(u64 v, float& lo, float& hi) {
    asm("mov.b64 {%0, %1}, %2;" : "=f"(lo), "=f"(hi) : "l"(v));
}

// ---------------- scratch (device globals; no runtime allocation) -------------
__device__ float g_zx[2][(size_t)NTOK * DPROJ];    // zxbcdt per direction
__device__ float g_xbc[2][(size_t)NTOK * CONVCH];  // post-conv silu(xBC)
__device__ float g_dt[2][NTOK * NHEADS];
__device__ float g_dA[2][NTOK * NHEADS];
__device__ float g_y[2][(size_t)NTOK * DINNER];    // scan output + D-skip
__device__ float g_gn[2][(size_t)NTOK * DINNER];   // gated-rmsnormed
__device__ float g_cat[(size_t)NTOK * 2 * DMODEL]; // concat of per-dir outputs

// ---------------- fp32 SGEMM with packed FFMA2: C = A[M,K] @ B[K,N] (+bias) ---
// 128x128 block tile, BK=8, 256 threads, 8x8 microtile (acc packed 8x4 f32x2).
__global__ __launch_bounds__(256, 2)
void sgemm128(const float* __restrict__ A, int lda,
              const float* __restrict__ B, int ldb,
              float* __restrict__ C, int ldc, int c_col_off,
              int M, int N, int K, int revA, int revC,
              const float* __restrict__ bias)
{
    __shared__ float As[8][128];
    __shared__ float Bs[8][128];

    const int tid = threadIdx.x;
    const int bn = blockIdx.x * 128;
    const int bm = blockIdx.y * 128;

    const int a_row = tid >> 1;
    const int a_col = (tid & 1) * 4;
    int am = bm + a_row;
    if (revA) { int bb = am >> 10; int ll = am & 1023; am = (bb << 10) + (1023 - ll); }
    const float* Aptr = A + (size_t)am * lda + a_col;

    const int b_row = tid >> 5;
    const int b_col = (tid & 31) * 4;
    const float* Bptr = B + (size_t)b_row * ldb + (bn + b_col);
    const bool b_ok = (bn + b_col) < N;   // N % 4 == 0 in all uses

    u64 acc2[8][4];
#pragma unroll
    for (int i = 0; i < 8; i++)
#pragma unroll
        for (int j = 0; j < 4; j++) acc2[i][j] = 0ull;

    const int tx = tid & 15;
    const int ty = tid >> 4;

    for (int k0 = 0; k0 < K; k0 += 8) {
        float4 av = *(const float4*)(Aptr + k0);
        float4 bv = make_float4(0.f, 0.f, 0.f, 0.f);
        if (b_ok) bv = *(const float4*)(Bptr + (size_t)k0 * ldb);

        As[a_col + 0][a_row] = av.x;
        As[a_col + 1][a_row] = av.y;
        As[a_col + 2][a_row] = av.z;
        As[a_col + 3][a_row] = av.w;
        *(float4*)&Bs[b_row][b_col] = bv;
        __syncthreads();

#pragma unroll
        for (int k = 0; k < 8; k++) {
            float4 a0 = *(const float4*)&As[k][ty * 8];
            float4 a1 = *(const float4*)&As[k][ty * 8 + 4];
            // b pairs: 4 x 64-bit packed loads
            const u64* bp = (const u64*)&Bs[k][tx * 8];
            u64 b2[4];
            b2[0] = bp[0]; b2[1] = bp[1]; b2[2] = bp[2]; b2[3] = bp[3];
            u64 a2[8];
            a2[0] = dup2(a0.x); a2[1] = dup2(a0.y); a2[2] = dup2(a0.z); a2[3] = dup2(a0.w);
            a2[4] = dup2(a1.x); a2[5] = dup2(a1.y); a2[6] = dup2(a1.z); a2[7] = dup2(a1.w);
#pragma unroll
            for (int i = 0; i < 8; i++)
#pragma unroll
                for (int j = 0; j < 4; j++)
                    acc2[i][j] = fma2(a2[i], b2[j], acc2[i][j]);
        }
        __syncthreads();
    }

#pragma unroll
    for (int i = 0; i < 8; i++) {
        int m = bm + ty * 8 + i;
        int mw = m;
        if (revC) { int bb = m >> 10; int ll = m & 1023; mw = (bb << 10) + (1023 - ll); }
        float* Crow = C + (size_t)mw * ldc + c_col_off;
#pragma unroll
        for (int j = 0; j < 4; j++) {
            float lo, hi;
            unpack2(acc2[i][j], lo, hi);
            int n = bn + tx * 8 + 2 * j;
            if (n < N) {
                float v = lo;
                if (bias) v += bias[n];
                Crow[n] = v;
            }
            if (n + 1 < N) {
                float v = hi;
                if (bias) v += bias[n + 1];
                Crow[n + 1] = v;
            }
        }
    }
}

// ---------------- conv (causal depthwise, 4 taps) + silu + dt/dA --------------
__global__ __launch_bounds__(256)
void conv_silu_dt(const float* __restrict__ cw0, const float* __restrict__ cb0,
                  const float* __restrict__ dtb0, const float* __restrict__ Al0,
                  const float* __restrict__ cw1, const float* __restrict__ cb1,
                  const float* __restrict__ dtb1, const float* __restrict__ Al1)
{
    const int dir = blockIdx.z;
    const int b = blockIdx.y;
    const int l = blockIdx.x;
    const float* cw  = dir ? cw1  : cw0;
    const float* cb  = dir ? cb1  : cb0;
    const float* dtb = dir ? dtb1 : dtb0;
    const float* Al  = dir ? Al1  : Al0;

    const float* zx = g_zx[dir];
    const int row = b * LSEQ + l;
    float* out = g_xbc[dir] + (size_t)row * CONVCH;

    for (int c = threadIdx.x; c < CONVCH; c += 256) {
        float acc = cb[c];
#pragma unroll
        for (int j = 0; j < 4; j++) {
            int ls = l - 3 + j;
            if (ls >= 0)
                acc = fmaf(cw[j * CONVCH + c],
                           zx[(size_t)(b * LSEQ + ls) * DPROJ + DINNER + c], acc);
        }
        out[c] = acc * (1.f / (1.f + expf(-acc)));   // silu
    }

    for (int h = threadIdx.x; h < NHEADS; h += 256) {
        float v = zx[(size_t)row * DPROJ + DINNER + CONVCH + h] + dtb[h];
        float dt = (v > 20.f) ? v : log1pf(expf(v));   // softplus
        g_dt[dir][row * NHEADS + h] = dt;
        g_dA[dir][row * NHEADS + h] = expf(-expf(Al[h]) * dt);
    }
}

// ---------------- sequential selective scan (packed f32x2 states) -------------
// block = (h, b, dir); 256 threads: thread t -> p = t>>2, n-range [ (t&3)*16, +16 )
#define TCHUNK 16
__global__ __launch_bounds__(256)
void scan_kernel(const float* __restrict__ D0, const float* __restrict__ D1)
{
    const int h = blockIdx.x;
    const int b = blockIdx.y;
    const int dir = blockIdx.z;
    const float* xbc = g_xbc[dir];
    const float* dtp = g_dt[dir];
    const float* dAp = g_dA[dir];
    float* yout = g_y[dir];
    const float Dh = (dir ? D1 : D0)[h];

    __shared__ float Bs[TCHUNK][DSTATE];
    __shared__ float Cs[TCHUNK][DSTATE];
    __shared__ float Xs[TCHUNK][HEADDIM];
    __shared__ float dAs[TCHUNK], dts[TCHUNK];

    const int tid = threadIdx.x;
    const int p = tid >> 2;
    const int q = tid & 3;
    const int n0 = q * 16;

    u64 hs2[8];
#pragma unroll
    for (int i = 0; i < 8; i++) hs2[i] = 0ull;

    const int rowbase = b * LSEQ;
    for (int l0 = 0; l0 < LSEQ; l0 += TCHUNK) {
        for (int i = tid; i < TCHUNK * 64; i += 256) {
            int tt = i >> 6, j = i & 63;
            size_t r = (size_t)(rowbase + l0 + tt);
            Bs[tt][j] = xbc[r * CONVCH + DINNER + j];
            Cs[tt][j] = xbc[r * CONVCH + DINNER + DSTATE + j];
            Xs[tt][j] = xbc[r * CONVCH + h * HEADDIM + j];
        }
        if (tid < TCHUNK) {
            size_t r = (size_t)(rowbase + l0 + tid);
            dAs[tid] = dAp[r * NHEADS + h];
            dts[tid] = dtp[r * NHEADS + h];
        }
        __syncthreads();

#pragma unroll
        for (int tt = 0; tt < TCHUNK; tt++) {
            float xp = Xs[tt][p];
            u64 da2 = dup2(dAs[tt]);
            u64 coef2 = dup2(dts[tt] * xp);
            u64 ysum2 = 0ull;
            const u64* Bv = (const u64*)&Bs[tt][n0];
            const u64* Cv = (const u64*)&Cs[tt][n0];
#pragma unroll
            for (int i = 0; i < 8; i++) {
                u64 bb = Bv[i];
                u64 cc = Cv[i];
                hs2[i] = fma2(da2, hs2[i], mul2(coef2, bb));
                ysum2 = fma2(cc, hs2[i], ysum2);
            }
            float ylo, yhi;
            unpack2(ysum2, ylo, yhi);
            float ysum = ylo + yhi;
            ysum += __shfl_xor_sync(0xffffffffu, ysum, 1);
            ysum += __shfl_xor_sync(0xffffffffu, ysum, 2);
            if (q == 0)
                yout[(size_t)(rowbase + l0 + tt) * DINNER + h * HEADDIM + p] =
                    ysum + Dh * xp;
        }
        __syncthreads();
    }
}

// ---------------- gated RMSNorm: gn = normw * (y*silu(z)) * rsqrt(mean+eps) ---
__global__ __launch_bounds__(256)
void gated_norm(const float* __restrict__ nw0, const float* __restrict__ nw1)
{
    const int dir = blockIdx.y;
    const int row = blockIdx.x;
    const float* nw = dir ? nw1 : nw0;
    const float* y = g_y[dir] + (size_t)row * DINNER;
    const float* z = g_zx[dir] + (size_t)row * DPROJ;   // z = first DINNER cols
    float* o = g_gn[dir] + (size_t)row * DINNER;

    float vals[8];
    float ss = 0.f;
#pragma unroll
    for (int i = 0; i < 8; i++) {
        int c = threadIdx.x + i * 256;
        float zz = z[c];
        float g = y[c] * (zz / (1.f + expf(-zz)));
        vals[i] = g;
        ss = fmaf(g, g, ss);
    }
#pragma unroll
    for (int o2 = 16; o2; o2 >>= 1) ss += __shfl_xor_sync(0xffffffffu, ss, o2);
    __shared__ float red[8];
    if ((threadIdx.x & 31) == 0) red[threadIdx.x >> 5] = ss;
    __syncthreads();
    float tot = red[0] + red[1] + red[2] + red[3] + red[4] + red[5] + red[6] + red[7];
    float scale = rsqrtf(tot * (1.f / DINNER) + 1e-5f);
#pragma unroll
    for (int i = 0; i < 8; i++) {
        int c = threadIdx.x + i * 256;
        o[c] = vals[i] * scale * nw[c];
    }
}

// ---------------- launch ----------------
extern "C" void kernel_launch(void* const* d_in, const int* in_sizes, int n_in,
                              void* d_out, int out_size)
{
    (void)in_sizes; (void)n_in; (void)out_size;
    const float* x      = (const float*)d_in[0];
    const float* fWin   = (const float*)d_in[1];
    const float* fconvw = (const float*)d_in[2];
    const float* fconvb = (const float*)d_in[3];
    const float* fdtb   = (const float*)d_in[4];
    const float* fAlog  = (const float*)d_in[5];
    const float* fD     = (const float*)d_in[6];
    const float* fnormw = (const float*)d_in[7];
    const float* fWout  = (const float*)d_in[8];
    const float* bWin   = (const float*)d_in[9];
    const float* bconvw = (const float*)d_in[10];
    const float* bconvb = (const float*)d_in[11];
    const float* bdtb   = (const float*)d_in[12];
    const float* bAlog  = (const float*)d_in[13];
    const float* bD     = (const float*)d_in[14];
    const float* bnormw = (const float*)d_in[15];
    const float* bWout  = (const float*)d_in[16];
    const float* Wo     = (const float*)d_in[17];
    const float* bo     = (const float*)d_in[18];
    float* out = (float*)d_out;

    float *zx, *gn, *cat;
    cudaGetSymbolAddress((void**)&zx, g_zx);
    cudaGetSymbolAddress((void**)&gn, g_gn);
    cudaGetSymbolAddress((void**)&cat, g_cat);
    float* zx0 = zx;
    float* zx1 = zx + (size_t)NTOK * DPROJ;
    float* gn0 = gn;
    float* gn1 = gn + (size_t)NTOK * DINNER;

    // 1) input projections (dir1 reads x sequence-reversed)
    dim3 g1((DPROJ + 127) / 128, NTOK / 128);
    sgemm128<<<g1, 256>>>(x, DMODEL, fWin, DPROJ, zx0, DPROJ, 0,
                          NTOK, DPROJ, DMODEL, 0, 0, nullptr);
    sgemm128<<<g1, 256>>>(x, DMODEL, bWin, DPROJ, zx1, DPROJ, 0,
                          NTOK, DPROJ, DMODEL, 1, 0, nullptr);

    // 2) causal conv + silu + dt/dA
    conv_silu_dt<<<dim3(LSEQ, BSZ, 2), 256>>>(fconvw, fconvb, fdtb, fAlog,
                                              bconvw, bconvb, bdtb, bAlog);

    // 3) selective scan
    scan_kernel<<<dim3(NHEADS, BSZ, 2), 256>>>(fD, bD);

    // 4) gated RMSNorm
    gated_norm<<<dim3(NTOK, 2), 256>>>(fnormw, bnormw);

    // 5) per-direction output projections into concat buffer (dir1 rows flipped back)
    dim3 g2(DMODEL / 128, NTOK / 128);
    sgemm128<<<g2, 256>>>(gn0, DINNER, fWout, DMODEL, cat, 2 * DMODEL, 0,
                          NTOK, DMODEL, DINNER, 0, 0, nullptr);
    sgemm128<<<g2, 256>>>(gn1, DINNER, bWout, DMODEL, cat, 2 * DMODEL, DMODEL,
                          NTOK, DMODEL, DINNER, 0, 1, nullptr);

    // 6) final projection + bias
    sgemm128<<<g2, 256>>>(cat, 2 * DMODEL, Wo, DMODEL, out, DMODEL, 0,
                          NTOK, DMODEL, 2 * DMODEL, 0, 0, bo);
}

// round 3
// speedup vs baseline: 1.6276x; 1.4476x over previous
#include <cuda_runtime.h>
#include <math.h>

#define BSZ 2
#define LSEQ 1024
#define DMODEL 1024
#define DINNER 2048
#define DSTATE 64
#define NHEADS 32
#define HEADDIM 64
#define CONVCH 2176
#define DPROJ 4256
#define NTOK 2048    // BSZ*LSEQ

typedef unsigned long long u64;
typedef unsigned int u32;

// ---------------- f32x2 packed-math helpers (scan) -----------------
__device__ __forceinline__ u64 dup2(float v) {
    u64 r; asm("mov.b64 %0, {%1, %1};" : "=l"(r) : "f"(v)); return r;
}
__device__ __forceinline__ u64 fma2(u64 a, u64 b, u64 c) {
    u64 d; asm("fma.rn.f32x2 %0, %1, %2, %3;" : "=l"(d) : "l"(a), "l"(b), "l"(c)); return d;
}
__device__ __forceinline__ u64 mul2(u64 a, u64 b) {
    u64 d; asm("mul.rn.f32x2 %0, %1, %2;" : "=l"(d) : "l"(a), "l"(b)); return d;
}
__device__ __forceinline__ void unpack2(u64 v, float& lo, float& hi) {
    asm("mov.b64 {%0, %1}, %2;" : "=f"(lo), "=f"(hi) : "l"(v));
}

// ---------------- tf32 helpers -----------------
__device__ __forceinline__ u32 to_tf32(float v) {
    u32 r; asm("cvt.rna.tf32.f32 %0, %1;" : "=r"(r) : "f"(v)); return r;
}
__device__ __forceinline__ void split_tf32(float v, u32& hi, u32& lo) {
    hi = to_tf32(v);
    lo = to_tf32(v - __uint_as_float(hi));
}
__device__ __forceinline__ void mma_tf32(float* d, const u32* a, const u32* b) {
    asm volatile(
        "mma.sync.aligned.m16n8k8.row.col.f32.tf32.tf32.f32 "
        "{%0,%1,%2,%3}, {%4,%5,%6,%7}, {%8,%9}, {%0,%1,%2,%3};"
        : "+f"(d[0]), "+f"(d[1]), "+f"(d[2]), "+f"(d[3])
        : "r"(a[0]), "r"(a[1]), "r"(a[2]), "r"(a[3]), "r"(b[0]), "r"(b[1]));
}

// ---------------- scratch (device globals; no runtime allocation) -------------
__device__ float g_zx[2][(size_t)NTOK * DPROJ];    // zxbcdt per direction
__device__ float g_xbc[2][(size_t)NTOK * CONVCH];  // post-conv silu(xBC)
__device__ float g_dt[2][NTOK * NHEADS];
__device__ float g_dA[2][NTOK * NHEADS];
__device__ float g_y[2][(size_t)NTOK * DINNER];    // scan output + D-skip
__device__ float g_gn[2][(size_t)NTOK * DINNER];   // gated-rmsnormed
__device__ float g_cat[(size_t)NTOK * 2 * DMODEL]; // concat of per-dir outputs

// ---------------- 3xTF32 tensor-core GEMM: C = A[M,K] @ B[K,N] (+bias) --------
// 128x128 block tile, BK=16, 256 threads (8 warps, 2x4), warp tile 64x32,
// m16n8k8 mma, hi/lo split for fp32-level accuracy. Double-buffered smem.
#define PADW 136

__global__ __launch_bounds__(256)
void tgemm(const float* __restrict__ A, int lda,
           const float* __restrict__ B, int ldb,
           float* __restrict__ C, int ldc, int c_col_off,
           int M, int N, int K, int revA, int revC,
           const float* __restrict__ bias)
{
    __shared__ float As[2][16][PADW];
    __shared__ float Bs[2][16][PADW];

    const int tid = threadIdx.x;
    const int bn = blockIdx.x * 128;
    const int bm = blockIdx.y * 128;

    const int wid = tid >> 5;
    const int lane = tid & 31;
    const int warp_m = wid >> 2;          // 0..1
    const int warp_n = wid & 3;           // 0..3
    const int g = lane >> 2;              // 0..7
    const int c = lane & 3;               // 0..3
    const int m_warp = warp_m * 64;
    const int n_warp = warp_n * 32;

    // A staging: thread loads 8 floats of one row: row = tid/2, kcols (tid&1)*8..+7
    const int a_row = tid >> 1;
    const int a_col8 = (tid & 1) * 8;
    int am = bm + a_row;
    if (revA) { int bb = am >> 10; int ll = am & 1023; am = (bb << 10) + (1023 - ll); }
    const float* Aptr = A + (size_t)am * lda + a_col8;

    // B staging: thread loads rows tid/32 and tid/32+8, cols (tid&31)*4..+3
    const int b_row = tid >> 5;
    const int b_col = (tid & 31) * 4;
    const float* Bptr = B + bn + b_col;
    const bool b_ok = (bn + b_col) < N;

    float acc[4][4][4];
#pragma unroll
    for (int i = 0; i < 4; i++)
#pragma unroll
        for (int j = 0; j < 4; j++)
#pragma unroll
            for (int r = 0; r < 4; r++) acc[i][j][r] = 0.f;

    const int nk = K / 16;

    // prologue: stage iter 0 into buffer 0
    {
        float4 pa0 = *(const float4*)(Aptr + 0);
        float4 pa1 = *(const float4*)(Aptr + 4);
        float4 pb0 = make_float4(0.f,0.f,0.f,0.f), pb1 = pb0;
        if (b_ok) {
            pb0 = *(const float4*)(Bptr + (size_t)b_row * ldb);
            pb1 = *(const float4*)(Bptr + (size_t)(b_row + 8) * ldb);
        }
        As[0][a_col8 + 0][a_row] = pa0.x; As[0][a_col8 + 1][a_row] = pa0.y;
        As[0][a_col8 + 2][a_row] = pa0.z; As[0][a_col8 + 3][a_row] = pa0.w;
        As[0][a_col8 + 4][a_row] = pa1.x; As[0][a_col8 + 5][a_row] = pa1.y;
        As[0][a_col8 + 6][a_row] = pa1.z; As[0][a_col8 + 7][a_row] = pa1.w;
        *(float4*)&Bs[0][b_row][b_col] = pb0;
        *(float4*)&Bs[0][b_row + 8][b_col] = pb1;
    }
    __syncthreads();

    for (int it = 0; it < nk; it++) {
        const int buf = it & 1;
        // prefetch next tile into registers
        float4 pa0, pa1, pb0, pb1;
        const bool more = (it + 1) < nk;
        if (more) {
            int kk = (it + 1) * 16;
            pa0 = *(const float4*)(Aptr + kk);
            pa1 = *(const float4*)(Aptr + kk + 4);
            pb0 = make_float4(0.f,0.f,0.f,0.f); pb1 = pb0;
            if (b_ok) {
                pb0 = *(const float4*)(Bptr + (size_t)(kk + b_row) * ldb);
                pb1 = *(const float4*)(Bptr + (size_t)(kk + b_row + 8) * ldb);
            }
        }

        // compute 2 k-steps of 8
#pragma unroll
        for (int ks = 0; ks < 2; ks++) {
            const int k0 = ks * 8;
            // B fragments (4 n-tiles), hi/lo
            u32 bh[4][2], bl[4][2];
#pragma unroll
            for (int in = 0; in < 4; in++) {
                int n0 = n_warp + in * 8 + g;
                float v0 = Bs[buf][k0 + c][n0];
                float v1 = Bs[buf][k0 + c + 4][n0];
                split_tf32(v0, bh[in][0], bl[in][0]);
                split_tf32(v1, bh[in][1], bl[in][1]);
            }
#pragma unroll
            for (int im = 0; im < 4; im++) {
                int m0 = m_warp + im * 16 + g;
                float v0 = As[buf][k0 + c][m0];
                float v1 = As[buf][k0 + c][m0 + 8];
                float v2 = As[buf][k0 + c + 4][m0];
                float v3 = As[buf][k0 + c + 4][m0 + 8];
                u32 ah[4], al[4];
                split_tf32(v0, ah[0], al[0]);
                split_tf32(v1, ah[1], al[1]);
                split_tf32(v2, ah[2], al[2]);
                split_tf32(v3, ah[3], al[3]);
#pragma unroll
                for (int in = 0; in < 4; in++) {
                    mma_tf32(acc[im][in], ah, bh[in]);   // hi*hi
                    mma_tf32(acc[im][in], al, bh[in]);   // lo*hi
                    mma_tf32(acc[im][in], ah, bl[in]);   // hi*lo
                }
            }
        }

        if (more) {
            const int nb = buf ^ 1;
            As[nb][a_col8 + 0][a_row] = pa0.x; As[nb][a_col8 + 1][a_row] = pa0.y;
            As[nb][a_col8 + 2][a_row] = pa0.z; As[nb][a_col8 + 3][a_row] = pa0.w;
            As[nb][a_col8 + 4][a_row] = pa1.x; As[nb][a_col8 + 5][a_row] = pa1.y;
            As[nb][a_col8 + 6][a_row] = pa1.z; As[nb][a_col8 + 7][a_row] = pa1.w;
            *(float4*)&Bs[nb][b_row][b_col] = pb0;
            *(float4*)&Bs[nb][b_row + 8][b_col] = pb1;
        }
        __syncthreads();
    }

    // epilogue
#pragma unroll
    for (int im = 0; im < 4; im++) {
        int mrow0 = bm + m_warp + im * 16 + g;
        int mrow1 = mrow0 + 8;
        int w0 = mrow0, w1 = mrow1;
        if (revC) {
            int bb = mrow0 >> 10, ll = mrow0 & 1023; w0 = (bb << 10) + (1023 - ll);
            bb = mrow1 >> 10; ll = mrow1 & 1023; w1 = (bb << 10) + (1023 - ll);
        }
        float* C0 = C + (size_t)w0 * ldc + c_col_off;
        float* C1 = C + (size_t)w1 * ldc + c_col_off;
#pragma unroll
        for (int in = 0; in < 4; in++) {
            int n0 = bn + n_warp + in * 8 + c * 2;
            float b0 = 0.f, b1 = 0.f;
            if (bias) {
                if (n0 < N) b0 = bias[n0];
                if (n0 + 1 < N) b1 = bias[n0 + 1];
            }
            if (n0 < N)     { C0[n0]     = acc[im][in][0] + b0; }
            if (n0 + 1 < N) { C0[n0 + 1] = acc[im][in][1] + b1; }
            if (n0 < N)     { C1[n0]     = acc[im][in][2] + b0; }
            if (n0 + 1 < N) { C1[n0 + 1] = acc[im][in][3] + b1; }
        }
    }
}

// ---------------- conv (causal depthwise, 4 taps) + silu + dt/dA --------------
__global__ __launch_bounds__(256)
void conv_silu_dt(const float* __restrict__ cw0, const float* __restrict__ cb0,
                  const float* __restrict__ dtb0, const float* __restrict__ Al0,
                  const float* __restrict__ cw1, const float* __restrict__ cb1,
                  const float* __restrict__ dtb1, const float* __restrict__ Al1)
{
    const int dir = blockIdx.z;
    const int b = blockIdx.y;
    const int l = blockIdx.x;
    const float* cw  = dir ? cw1  : cw0;
    const float* cb  = dir ? cb1  : cb0;
    const float* dtb = dir ? dtb1 : dtb0;
    const float* Al  = dir ? Al1  : Al0;

    const float* zx = g_zx[dir];
    const int row = b * LSEQ + l;
    float* out = g_xbc[dir] + (size_t)row * CONVCH;

    for (int c = threadIdx.x; c < CONVCH; c += 256) {
        float acc = cb[c];
#pragma unroll
        for (int j = 0; j < 4; j++) {
            int ls = l - 3 + j;
            if (ls >= 0)
                acc = fmaf(cw[j * CONVCH + c],
                           zx[(size_t)(b * LSEQ + ls) * DPROJ + DINNER + c], acc);
        }
        out[c] = acc * (1.f / (1.f + expf(-acc)));   // silu
    }

    for (int h = threadIdx.x; h < NHEADS; h += 256) {
        float v = zx[(size_t)row * DPROJ + DINNER + CONVCH + h] + dtb[h];
        float dt = (v > 20.f) ? v : log1pf(expf(v));   // softplus
        g_dt[dir][row * NHEADS + h] = dt;
        g_dA[dir][row * NHEADS + h] = expf(-expf(Al[h]) * dt);
    }
}

// ---------------- sequential selective scan (packed f32x2 states) -------------
#define TCHUNK 16
__global__ __launch_bounds__(256)
void scan_kernel(const float* __restrict__ D0, const float* __restrict__ D1)
{
    const int h = blockIdx.x;
    const int b = blockIdx.y;
    const int dir = blockIdx.z;
    const float* xbc = g_xbc[dir];
    const float* dtp = g_dt[dir];
    const float* dAp = g_dA[dir];
    float* yout = g_y[dir];
    const float Dh = (dir ? D1 : D0)[h];

    __shared__ float Bs[TCHUNK][DSTATE];
    __shared__ float Cs[TCHUNK][DSTATE];
    __shared__ float Xs[TCHUNK][HEADDIM];
    __shared__ float dAs[TCHUNK], dts[TCHUNK];

    const int tid = threadIdx.x;
    const int p = tid >> 2;
    const int q = tid & 3;
    const int n0 = q * 16;

    u64 hs2[8];
#pragma unroll
    for (int i = 0; i < 8; i++) hs2[i] = 0ull;

    const int rowbase = b * LSEQ;
    for (int l0 = 0; l0 < LSEQ; l0 += TCHUNK) {
        for (int i = tid; i < TCHUNK * 64; i += 256) {
            int tt = i >> 6, j = i & 63;
            size_t r = (size_t)(rowbase + l0 + tt);
            Bs[tt][j] = xbc[r * CONVCH + DINNER + j];
            Cs[tt][j] = xbc[r * CONVCH + DINNER + DSTATE + j];
            Xs[tt][j] = xbc[r * CONVCH + h * HEADDIM + j];
        }
        if (tid < TCHUNK) {
            size_t r = (size_t)(rowbase + l0 + tid);
            dAs[tid] = dAp[r * NHEADS + h];
            dts[tid] = dtp[r * NHEADS + h];
        }
        __syncthreads();

#pragma unroll
        for (int tt = 0; tt < TCHUNK; tt++) {
            float xp = Xs[tt][p];
            u64 da2 = dup2(dAs[tt]);
            u64 coef2 = dup2(dts[tt] * xp);
            u64 ysum2 = 0ull;
            const u64* Bv = (const u64*)&Bs[tt][n0];
            const u64* Cv = (const u64*)&Cs[tt][n0];
#pragma unroll
            for (int i = 0; i < 8; i++) {
                u64 bb = Bv[i];
                u64 cc = Cv[i];
                hs2[i] = fma2(da2, hs2[i], mul2(coef2, bb));
                ysum2 = fma2(cc, hs2[i], ysum2);
            }
            float ylo, yhi;
            unpack2(ysum2, ylo, yhi);
            float ysum = ylo + yhi;
            ysum += __shfl_xor_sync(0xffffffffu, ysum, 1);
            ysum += __shfl_xor_sync(0xffffffffu, ysum, 2);
            if (q == 0)
                yout[(size_t)(rowbase + l0 + tt) * DINNER + h * HEADDIM + p] =
                    ysum + Dh * xp;
        }
        __syncthreads();
    }
}

// ---------------- gated RMSNorm: gn = normw * (y*silu(z)) * rsqrt(mean+eps) ---
__global__ __launch_bounds__(256)
void gated_norm(const float* __restrict__ nw0, const float* __restrict__ nw1)
{
    const int dir = blockIdx.y;
    const int row = blockIdx.x;
    const float* nw = dir ? nw1 : nw0;
    const float* y = g_y[dir] + (size_t)row * DINNER;
    const float* z = g_zx[dir] + (size_t)row * DPROJ;   // z = first DINNER cols
    float* o = g_gn[dir] + (size_t)row * DINNER;

    float vals[8];
    float ss = 0.f;
#pragma unroll
    for (int i = 0; i < 8; i++) {
        int c = threadIdx.x + i * 256;
        float zz = z[c];
        float g = y[c] * (zz / (1.f + expf(-zz)));
        vals[i] = g;
        ss = fmaf(g, g, ss);
    }
#pragma unroll
    for (int o2 = 16; o2; o2 >>= 1) ss += __shfl_xor_sync(0xffffffffu, ss, o2);
    __shared__ float red[8];
    if ((threadIdx.x & 31) == 0) red[threadIdx.x >> 5] = ss;
    __syncthreads();
    float tot = red[0] + red[1] + red[2] + red[3] + red[4] + red[5] + red[6] + red[7];
    float scale = rsqrtf(tot * (1.f / DINNER) + 1e-5f);
#pragma unroll
    for (int i = 0; i < 8; i++) {
        int c = threadIdx.x + i * 256;
        o[c] = vals[i] * scale * nw[c];
    }
}

// ---------------- launch ----------------
extern "C" void kernel_launch(void* const* d_in, const int* in_sizes, int n_in,
                              void* d_out, int out_size)
{
    (void)in_sizes; (void)n_in; (void)out_size;
    const float* x      = (const float*)d_in[0];
    const float* fWin   = (const float*)d_in[1];
    const float* fconvw = (const float*)d_in[2];
    const float* fconvb = (const float*)d_in[3];
    const float* fdtb   = (const float*)d_in[4];
    const float* fAlog  = (const float*)d_in[5];
    const float* fD     = (const float*)d_in[6];
    const float* fnormw = (const float*)d_in[7];
    const float* fWout  = (const float*)d_in[8];
    const float* bWin   = (const float*)d_in[9];
    const float* bconvw = (const float*)d_in[10];
    const float* bconvb = (const float*)d_in[11];
    const float* bdtb   = (const float*)d_in[12];
    const float* bAlog  = (const float*)d_in[13];
    const float* bD     = (const float*)d_in[14];
    const float* bnormw = (const float*)d_in[15];
    const float* bWout  = (const float*)d_in[16];
    const float* Wo     = (const float*)d_in[17];
    const float* bo     = (const float*)d_in[18];
    float* out = (float*)d_out;

    float *zx, *gn, *cat;
    cudaGetSymbolAddress((void**)&zx, g_zx);
    cudaGetSymbolAddress((void**)&gn, g_gn);
    cudaGetSymbolAddress((void**)&cat, g_cat);
    float* zx0 = zx;
    float* zx1 = zx + (size_t)NTOK * DPROJ;
    float* gn0 = gn;
    float* gn1 = gn + (size_t)NTOK * DINNER;

    // 1) input projections (dir1 reads x sequence-reversed)
    dim3 g1((DPROJ + 127) / 128, NTOK / 128);
    tgemm<<<g1, 256>>>(x, DMODEL, fWin, DPROJ, zx0, DPROJ, 0,
                       NTOK, DPROJ, DMODEL, 0, 0, nullptr);
    tgemm<<<g1, 256>>>(x, DMODEL, bWin, DPROJ, zx1, DPROJ, 0,
                       NTOK, DPROJ, DMODEL, 1, 0, nullptr);

    // 2) causal conv + silu + dt/dA
    conv_silu_dt<<<dim3(LSEQ, BSZ, 2), 256>>>(fconvw, fconvb, fdtb, fAlog,
                                              bconvw, bconvb, bdtb, bAlog);

    // 3) selective scan
    scan_kernel<<<dim3(NHEADS, BSZ, 2), 256>>>(fD, bD);

    // 4) gated RMSNorm
    gated_norm<<<dim3(NTOK, 2), 256>>>(fnormw, bnormw);

    // 5) per-direction output projections into concat buffer (dir1 rows flipped back)
    dim3 g2(DMODEL / 128, NTOK / 128);
    tgemm<<<g2, 256>>>(gn0, DINNER, fWout, DMODEL, cat, 2 * DMODEL, 0,
                       NTOK, DMODEL, DINNER, 0, 0, nullptr);
    tgemm<<<g2, 256>>>(gn1, DINNER, bWout, DMODEL, cat, 2 * DMODEL, DMODEL,
                       NTOK, DMODEL, DINNER, 0, 1, nullptr);

    // 6) final projection + bias
    tgemm<<<g2, 256>>>(cat, 2 * DMODEL, Wo, DMODEL, out, DMODEL, 0,
                       NTOK, DMODEL, 2 * DMODEL, 0, 0, bo);
}